// round 14
// baseline (speedup 1.0000x reference)
#include <cuda_runtime.h>

#define B_VOX   256
#define NPC     40
#define NE      32
#define ORD     8                    // EPG orders per lane (4 packed pairs)
#define NPK     (ORD / 2)            // 4 f32x2 pairs
#define LPC     4                    // lanes per compartment (32 orders)
#define CPW     8                    // compartments per warp
#define VPB     2                    // voxels per block (grid=128: measured optimum)
#define WARPS_V (NPC / CPW)          // 5 warps per voxel
#define WARPS   (WARPS_V * VPB)      // 10 warps per block
#define THREADS (WARPS * 32)         // 320

typedef unsigned long long ull;

__device__ __forceinline__ ull f2pk(float lo, float hi) {
    ull r; asm("mov.b64 %0, {%1, %2};" : "=l"(r) : "f"(lo), "f"(hi)); return r;
}
__device__ __forceinline__ void f2unpk(ull v, float& lo, float& hi) {
    asm("mov.b64 {%0, %1}, %2;" : "=f"(lo), "=f"(hi) : "l"(v));
}
__device__ __forceinline__ ull mul2(ull a, ull b) {
    ull r; asm("mul.rn.f32x2 %0, %1, %2;" : "=l"(r) : "l"(a), "l"(b)); return r;
}
__device__ __forceinline__ ull fma2(ull a, ull b, ull c) {
    ull r; asm("fma.rn.f32x2 %0, %1, %2, %3;" : "=l"(r) : "l"(a), "l"(b), "l"(c)); return r;
}

// y-form EPG: y_{k+1} = S^2·M·y_k, orders packed 2-per-register so the
// 2-order shift = one-register shift; boundary = one 64-bit shfl per side.
// Per pair:  mF2 = A·F2 + B·G2 + u2 ;  mG2 = B·F2 + A·G2 - u2
//            u2' = CD·G2 - CD·F2 + Ez·u2       (u = C·Z)
// s0 fixup: F2[0] <- (mG[0], e2²·x0);  s3 fixup: G2[3] <- 0
// echo_k = lo(mG2[0]);  x0' = hi(mG2[0])

__global__ __launch_bounds__(THREADS) void epg_kernel(
    const float* __restrict__ refoc,    // (256,)
    const float* __restrict__ t2s,      // (256, 40)
    const float* __restrict__ wts,      // (256, 40)
    float* __restrict__ out)            // (256, 32)
{
    const int lane = threadIdx.x & 31;
    const int wz   = threadIdx.x >> 5;
    const int vv   = wz / WARPS_V;
    const int wv   = wz % WARPS_V;
    const int b    = blockIdx.x * VPB + vv;
    const int s    = lane & (LPC - 1);
    const int grp  = lane >> 2;
    const bool sLo = (s == 0);
    const bool sHi = (s == LPC - 1);
    const unsigned FULL = 0xFFFFFFFFu;

    __shared__ float smem[VPB][NPC][NE + 1];
    __shared__ float part[VPB][WARPS_V][NE];

    // global loads first (overlap with MUFU prologue)
    const int   c    = wv * CPW + grp;
    const float t2   = __ldg(&t2s[b * NPC + c]);
    const float w    = __ldg(&wts[b * NPC + c]);
    const float ang  = __ldg(&refoc[b]);

    // per-voxel rotation constants — fast MUFU path
    const float a  = ang * 0.017453292519943295f;
    const float sa = __sinf(a);
    const float ca = __cosf(a);
    const float c2 = 0.5f * (1.0f + ca);
    const float s2 = 0.5f * (1.0f - ca);
    const float ch = sqrtf(c2);
    const float sh = sqrtf(s2);
    const float e1   = 0.99501247919268231f;     // exp(-5/1000)
    const float e1sq = e1 * e1;

    // per-compartment fused coefficients
    const float e2   = __expf(-5.0f * __frcp_rn(t2));
    const float e2sq = e2 * e2;
    const float A    = c2 * e2sq;
    const float Bc   = s2 * e2sq;
    const float Cc   = sa * e2 * e1;
    const float Dz   = 0.5f * sa * e1 * e2;
    const float Ez   = ca * e1sq;
    const float CD   = Cc * Dz;

    // broadcast-packed coefficients
    const ull A2   = f2pk(A,   A);
    const ull B2   = f2pk(Bc,  Bc);
    const ull CD2  = f2pk(CD,  CD);
    const ull CDn2 = f2pk(-CD, -CD);
    const ull E2   = f2pk(Ez,  Ez);
    const ull N1   = f2pk(-1.f, -1.f);
    const ull Z64  = f2pk(0.f, 0.f);

    // init y0 = S·x0, weight folded in
    ull F2[NPK], G2[NPK], u2[NPK];
    #pragma unroll
    for (int j = 0; j < NPK; ++j) { F2[j] = Z64; G2[j] = Z64; u2[j] = Z64; }
    if (sLo) F2[0] = f2pk(w * sh, 0.f);
    float x0 = w * ch;                           // meaningful on sub-lane 0

    #pragma unroll                                // full unroll: shift = renaming
    for (int k = 0; k < NE; ++k) {
        ull mF[NPK], mG[NPK];
        #pragma unroll
        for (int j = 0; j < NPK; ++j) {
            mF[j] = fma2(A2, F2[j], fma2(B2, G2[j], u2[j]));
            const ull nu = mul2(u2[j], N1);
            mG[j] = fma2(B2, F2[j], fma2(A2, G2[j], nu));
            u2[j] = fma2(CD2, G2[j], fma2(CDn2, F2[j], mul2(E2, u2[j])));
        }
        const float mx0 = e2sq * x0;

        float g0lo, g0hi;
        f2unpk(mG[0], g0lo, g0hi);               // echo_k, next x0

        // boundary carries: one 64-bit shfl per direction (serves the pair)
        const ull cF = __shfl_up_sync  (FULL, mF[NPK-1], 1, LPC);
        const ull cG = __shfl_down_sync(FULL, mG[0],     1, LPC);

        if (sLo) smem[vv][c][k] = g0lo;          // pre-weighted echo

        F2[0] = sLo ? f2pk(g0lo, mx0) : cF;
        F2[1] = mF[0];  F2[2] = mF[1];  F2[3] = mF[2];
        G2[0] = mG[1];  G2[1] = mG[2];  G2[2] = mG[3];
        G2[3] = sHi ? Z64 : cG;
        x0 = g0hi;
    }

    // stage 1: each warp reduces its own 8 compartment rows
    __syncwarp();
    {
        float acc = 0.0f;
        #pragma unroll
        for (int g = 0; g < CPW; ++g) acc += smem[vv][wv * CPW + g][lane];
        part[vv][wv][lane] = acc;
    }
    __syncthreads();

    // stage 2: one warp per voxel sums 5 partials, normalizes by echo 0
    if (wv == 0) {
        float acc = 0.0f;
        #pragma unroll
        for (int ww = 0; ww < WARPS_V; ++ww) acc += part[vv][ww][lane];
        const float acc0 = __shfl_sync(FULL, acc, 0);
        out[b * NE + lane] = __fdividef(acc, acc0);
    }
}

extern "C" void kernel_launch(void* const* d_in, const int* in_sizes, int n_in,
                              void* d_out, int out_size) {
    const float* refoc = (const float*)d_in[0];
    const float* t2s   = (const float*)d_in[1];
    const float* wts   = (const float*)d_in[2];
    float* out = (float*)d_out;
    epg_kernel<<<B_VOX / VPB, THREADS>>>(refoc, t2s, wts, out);
}